// round 14
// baseline (speedup 1.0000x reference)
#include <cuda_runtime.h>
#include <cuda_bf16.h>
#include <cuda_fp16.h>
#include <math.h>
#include <stdint.h>

#define NN 100000
#define NE 1600000
#define FIN 165
#define F1  256
#define KP  176            // K padded to multiple of 16
#define KPW (KP/2)         // 32-bit words per row
#define EPSV 1e-16f

// ---------------- scratch (device globals; no allocations allowed) ----------
__device__ __align__(16) __half g_h1h[(size_t)NN * F1];   // fp16 h1 (51 MB)
__device__ __align__(16) float g_asrc1[NN * 4];
__device__ __align__(16) float g_adst1[NN * 4];
__device__ __align__(16) float g_gg[NN * 2];              // GEMM2 partial sums
__device__ __align__(16) float4 g_pack[NN];               // {asrc2, g0, g1, -}
__device__ float g_adst2[NN];
// bf16 operands (x: hi only; W: hi+lo split — hi+lo is load-bearing, see R10)
__device__ __align__(16) __nv_bfloat16 g_xhi[(size_t)NN * KP];
__device__ __align__(16) __nv_bfloat16 g_whiT[256 * KP];
__device__ __align__(16) __nv_bfloat16 g_wloT[256 * KP];
// CSR scratch
__device__ int g_cnt[NN];
__device__ int g_row[NN + 1];
__device__ int g_cur[NN];
__device__ int g_esrc[NE];
__device__ int g_bsum[256];
__device__ int g_boff[256];

__device__ __forceinline__ float lrelu(float v) { return v > 0.f ? v : 0.2f * v; }

__device__ __forceinline__ void cpa16(uint32_t dst, const void* src, bool valid) {
    asm volatile("cp.async.cg.shared.global [%0], [%1], 16, %2;\n"
                 :: "r"(dst), "l"(src), "r"(valid ? 16 : 0));
}
__device__ __forceinline__ void cpa_commit() {
    asm volatile("cp.async.commit_group;\n");
}
template <int N>
__device__ __forceinline__ void cpa_wait() {
    asm volatile("cp.async.wait_group %0;\n" :: "n"(N));
}
__device__ __forceinline__ void ldsm4(uint32_t* r, uint32_t addr) {
    asm volatile("ldmatrix.sync.aligned.m8n8.x4.shared.b16 {%0,%1,%2,%3}, [%4];"
                 : "=r"(r[0]), "=r"(r[1]), "=r"(r[2]), "=r"(r[3]) : "r"(addr));
}

// --------- operand conversion + g_gg zeroing (one launch) -------------------
__global__ void k_cvtxw(const float* __restrict__ x, const float* __restrict__ W, int n) {
    int i = blockIdx.x * blockDim.x + threadIdx.x;
    int nx = n * KP;
    int nw = 256 * KP;
    if (i < nx) {
        int node = i / KP, k = i - node * KP;
        float v = (k < FIN) ? __ldg(&x[(size_t)node * FIN + k]) : 0.f;
        g_xhi[i] = __float2bfloat16(v);
    } else if (i < nx + nw) {
        int j = i - nx;
        int nc = j / KP, k = j - nc * KP;
        float v = (k < FIN) ? W[(size_t)k * 256 + nc] : 0.f;
        __nv_bfloat16 hi = __float2bfloat16(v);
        g_whiT[j] = hi;
        g_wloT[j] = __float2bfloat16(v - __bfloat162float(hi));
    } else {
        int j = i - nx - nw;
        if (j < n * 2) g_gg[j] = 0.f;
    }
}

// ---------------- tensor-core GEMM1 + fused attention scores ----------------
__device__ __forceinline__ void hmma(float* d, const uint32_t* a, const uint32_t* b) {
    asm volatile(
        "mma.sync.aligned.m16n8k16.row.col.f32.bf16.bf16.f32 "
        "{%0,%1,%2,%3},{%4,%5,%6,%7},{%8,%9},{%0,%1,%2,%3};\n"
        : "+f"(d[0]), "+f"(d[1]), "+f"(d[2]), "+f"(d[3])
        : "r"(a[0]), "r"(a[1]), "r"(a[2]), "r"(a[3]), "r"(b[0]), "r"(b[1]));
}

#define ASTRIDE 12          // padded word stride for A (conflict-free ldmatrix)
#define ABUF (128 * ASTRIDE)
#define BSTRIDE 92          // 88 kwords + 4 pad, per B row (conflict-free ldmatrix)
#define NIT  (KP / 16)      // 11 k-iterations

// block: 128 nodes x 64 cols (= one head). 256 threads = 8 warps (4m x 2n).
__global__ void __launch_bounds__(256) k_gemm1_mma(const float* __restrict__ att_s,
                                                   const float* __restrict__ att_d, int n) {
    __shared__ uint32_t sA[2 * ABUF];           // 12 KB
    __shared__ uint32_t sBh[64 * BSTRIDE];      // 23 KB
    __shared__ uint32_t sBl[64 * BSTRIDE];      // 23 KB
    __shared__ float sS[128], sD[128];
    int bm = blockIdx.y * 128, bn = blockIdx.x * 64, h = bn >> 6;
    int tid = threadIdx.x, lane = tid & 31, wid = tid >> 5;
    int wm = wid & 3, wn = wid >> 2, quad = lane >> 2, t4 = lane & 3;
    if (tid < 128) { sS[tid] = 0.f; sD[tid] = 0.f; }

    const uint32_t* xhi = (const uint32_t*)g_xhi;
    const uint32_t* whi = (const uint32_t*)g_whiT;
    const uint32_t* wlo = (const uint32_t*)g_wloT;

    uint32_t sA_b = (uint32_t)__cvta_generic_to_shared(sA);
    uint32_t sBh_b = (uint32_t)__cvta_generic_to_shared(sBh);
    uint32_t sBl_b = (uint32_t)__cvta_generic_to_shared(sBl);

    // ---- preload ALL of B (64 rows x 88 kwords, hi+lo) via 16B cp.async ----
    {
        for (int c = tid; c < 1408; c += 256) {
            int rowi = (c * 4) / 88;
            int kw = (c * 4) % 88;      // 88 % 4 == 0 -> chunks never cross rows
            cpa16(sBh_b + (rowi * BSTRIDE + kw) * 4, whi + (size_t)(bn + rowi) * KPW + kw, true);
            cpa16(sBl_b + (rowi * BSTRIDE + kw) * 4, wlo + (size_t)(bn + rowi) * KPW + kw, true);
        }
        cpa_commit();
    }

    // A loader: 128 rows x 8 kwords, one 16B cp.async per thread
    int a_row = tid >> 1, a_w4 = (tid & 1) * 4;
    auto loadA = [&](int it, int buf) {
        int kw = it * 8;
        int node = bm + a_row;
        cpa16(sA_b + (buf * ABUF + a_row * ASTRIDE + a_w4) * 4,
              xhi + (size_t)node * KPW + kw + a_w4, node < n);
        cpa_commit();
    };

    // ldmatrix lane addresses (byte offsets into smem)
    uint32_t aAddr = sA_b + (((wm * 32 + (lane & 15)) * ASTRIDE + ((lane >> 4) & 1) * 4)) * 4;
    uint32_t bRowOff = ((wn * 32 + (lane & 7) + ((lane >> 4) & 1) * 8) * BSTRIDE
                        + ((lane >> 3) & 1) * 4) * 4;
    uint32_t bhAddr = sBh_b + bRowOff;
    uint32_t blAddr = sBl_b + bRowOff;

    float d[2][4][4];
#pragma unroll
    for (int a = 0; a < 2; a++)
#pragma unroll
        for (int b = 0; b < 4; b++)
#pragma unroll
            for (int c = 0; c < 4; c++) d[a][b][c] = 0.f;

    loadA(0, 0);
    cpa_wait<0>();
    __syncthreads();

    for (int it = 0; it < NIT; it++) {
        int buf = it & 1;
        if (it + 1 < NIT) loadA(it + 1, buf ^ 1);

        uint32_t ah[2][4], bh01[4], bh23[4], bl01[4], bl23[4];
        uint32_t aBase = aAddr + buf * (ABUF * 4);
        ldsm4(ah[0], aBase);
        ldsm4(ah[1], aBase + 16 * ASTRIDE * 4);
        uint32_t kb = it * 32;   // 8 words per iter = 32 bytes
        ldsm4(bh01, bhAddr + kb);
        ldsm4(bh23, bhAddr + kb + 16 * BSTRIDE * 4);
        ldsm4(bl01, blAddr + kb);
        ldsm4(bl23, blAddr + kb + 16 * BSTRIDE * 4);

#pragma unroll
        for (int mt = 0; mt < 2; mt++) {
            hmma(d[mt][0], ah[mt], &bh01[0]);
            hmma(d[mt][1], ah[mt], &bh01[2]);
            hmma(d[mt][2], ah[mt], &bh23[0]);
            hmma(d[mt][3], ah[mt], &bh23[2]);
            hmma(d[mt][0], ah[mt], &bl01[0]);
            hmma(d[mt][1], ah[mt], &bl01[2]);
            hmma(d[mt][2], ah[mt], &bl23[0]);
            hmma(d[mt][3], ah[mt], &bl23[2]);
        }
        if (it + 1 < NIT) {
            cpa_wait<0>();
            __syncthreads();
        }
    }

    // store h1 (fp16) + accumulate attention-score partial dots
#pragma unroll
    for (int mt = 0; mt < 2; mt++) {
        int row = wm * 32 + mt * 16 + quad;
        int node0 = bm + row, node1 = node0 + 8;
        float s0 = 0.f, s1 = 0.f, dd0 = 0.f, dd1 = 0.f;
#pragma unroll
        for (int nt = 0; nt < 4; nt++) {
            int c = wn * 32 + nt * 8 + t4 * 2;
            float a0 = __ldg(&att_s[h * 64 + c]), a1 = __ldg(&att_s[h * 64 + c + 1]);
            float e0 = __ldg(&att_d[h * 64 + c]), e1 = __ldg(&att_d[h * 64 + c + 1]);
            s0  += d[mt][nt][0] * a0 + d[mt][nt][1] * a1;
            dd0 += d[mt][nt][0] * e0 + d[mt][nt][1] * e1;
            s1  += d[mt][nt][2] * a0 + d[mt][nt][3] * a1;
            dd1 += d[mt][nt][2] * e0 + d[mt][nt][3] * e1;
            if (node0 < n)
                *(__half2*)&g_h1h[(size_t)node0 * F1 + bn + c] = __floats2half2_rn(d[mt][nt][0], d[mt][nt][1]);
            if (node1 < n)
                *(__half2*)&g_h1h[(size_t)node1 * F1 + bn + c] = __floats2half2_rn(d[mt][nt][2], d[mt][nt][3]);
        }
        s0  += __shfl_xor_sync(0xffffffffu, s0, 1);  s0  += __shfl_xor_sync(0xffffffffu, s0, 2);
        s1  += __shfl_xor_sync(0xffffffffu, s1, 1);  s1  += __shfl_xor_sync(0xffffffffu, s1, 2);
        dd0 += __shfl_xor_sync(0xffffffffu, dd0, 1); dd0 += __shfl_xor_sync(0xffffffffu, dd0, 2);
        dd1 += __shfl_xor_sync(0xffffffffu, dd1, 1); dd1 += __shfl_xor_sync(0xffffffffu, dd1, 2);
        if (t4 == 0) {
            atomicAdd(&sS[row], s0); atomicAdd(&sD[row], dd0);
            atomicAdd(&sS[row + 8], s1); atomicAdd(&sD[row + 8], dd1);
        }
    }
    __syncthreads();
    if (tid < 128) {
        int node = bm + tid;
        if (node < n) {
            g_asrc1[node * 4 + h] = sS[tid];
            g_adst1[node * 4 + h] = sD[tid];
        }
    }
}

// ---------------- CSR build (group edges by dst) -----------------------------
__global__ void k_zerocnt(int n) {
    int i = blockIdx.x * blockDim.x + threadIdx.x;
    if (i < n) g_cnt[i] = 0;
}

__global__ void k_count(const int* __restrict__ dst, int e) {
    int i = blockIdx.x * blockDim.x + threadIdx.x;
    if (i < e) atomicAdd(&g_cnt[dst[i]], 1);
}

__global__ void k_scan1(int n) {
    __shared__ int sh[512];
    int t = threadIdx.x, i = blockIdx.x * 512 + t;
    sh[t] = (i < n) ? g_cnt[i] : 0;
    __syncthreads();
    for (int o = 256; o; o >>= 1) {
        if (t < o) sh[t] += sh[t + o];
        __syncthreads();
    }
    if (t == 0) g_bsum[blockIdx.x] = sh[0];
}

__global__ void k_scan2(int n, int nb) {
    __shared__ int sh[256];
    int t = threadIdx.x;
    int own = (t < nb) ? g_bsum[t] : 0;
    sh[t] = own;
    __syncthreads();
    for (int o = 1; o < 256; o <<= 1) {
        int v = (t >= o) ? sh[t - o] : 0;
        __syncthreads();
        sh[t] += v;
        __syncthreads();
    }
    if (t < nb) g_boff[t] = sh[t] - own;
    if (t == nb - 1) g_row[n] = sh[t];
}

__global__ void k_scan3(int n) {
    __shared__ int sh[512];
    int t = threadIdx.x, i = blockIdx.x * 512 + t;
    int own = (i < n) ? g_cnt[i] : 0;
    sh[t] = own;
    __syncthreads();
    for (int o = 1; o < 512; o <<= 1) {
        int v = (t >= o) ? sh[t - o] : 0;
        __syncthreads();
        sh[t] += v;
        __syncthreads();
    }
    if (i < n) {
        int excl = sh[t] - own + g_boff[blockIdx.x];
        g_row[i] = excl;
        g_cur[i] = excl;
    }
}

__global__ void k_scatter(const int* __restrict__ src, const int* __restrict__ dst, int e) {
    int i = blockIdx.x * blockDim.x + threadIdx.x;
    if (i >= e) return;
    int d = dst[i];
    int pos = atomicAdd(&g_cur[d], 1);
    g_esrc[pos] = src[i];
}

// ---- Layer-1 aggregation: warp per (node, head). 16-edge batched gathers ---
// Each lane owns 2 channels of the head (64 ch / 32 lanes, __half2 loads).
// Per-head softmax is warp-local; GEMM2 partials combine via atomicAdd(g_gg).
__global__ void __launch_bounds__(256) k_agg1f(const float* __restrict__ b1,
                                               const float* __restrict__ W2, int n) {
    int gw = (blockIdx.x * blockDim.x + threadIdx.x) >> 5;
    int lane = threadIdx.x & 31;
    int node = gw >> 2, head = gw & 3;
    if (node >= n) return;
    int ih = node * 4 + head;
    int coff = head * 64 + lane * 2;      // this lane's channel pair
    float adst = __ldg(&g_adst1[ih]);

    float s;
    float2 acc;
    {   // self-loop
        float wS = __expf(lrelu(__ldg(&g_asrc1[ih]) + adst));
        s = wS;
        __half2 hv = *(const __half2*)&g_h1h[(size_t)node * F1 + coff];
        float2 f = __half22float2(hv);
        acc.x = wS * f.x;
        acc.y = wS * f.y;
    }

    int beg = g_row[node], end = g_row[node + 1];
    int i = beg;
    for (; i + 15 < end; i += 16) {
        int sidx[16];
#pragma unroll
        for (int j = 0; j < 16; j++) sidx[j] = __ldg(&g_esrc[i + j]);
        float ew[16];
        uint32_t hv[16];
#pragma unroll
        for (int j = 0; j < 16; j++) {
            ew[j] = __ldg(&g_asrc1[sidx[j] * 4 + head]);
            hv[j] = __ldg((const uint32_t*)&g_h1h[(size_t)sidx[j] * F1 + coff]);
        }
#pragma unroll
        for (int j = 0; j < 16; j++) {
            float wt = __expf(lrelu(ew[j] + adst));
            s += wt;
            float2 f = __half22float2(*(__half2*)&hv[j]);
            acc.x = fmaf(wt, f.x, acc.x);
            acc.y = fmaf(wt, f.y, acc.y);
        }
    }
    for (; i + 3 < end; i += 4) {
        int sidx[4];
#pragma unroll
        for (int j = 0; j < 4; j++) sidx[j] = __ldg(&g_esrc[i + j]);
        float ew[4];
        uint32_t hv[4];
#pragma unroll
        for (int j = 0; j < 4; j++) {
            ew[j] = __ldg(&g_asrc1[sidx[j] * 4 + head]);
            hv[j] = __ldg((const uint32_t*)&g_h1h[(size_t)sidx[j] * F1 + coff]);
        }
#pragma unroll
        for (int j = 0; j < 4; j++) {
            float wt = __expf(lrelu(ew[j] + adst));
            s += wt;
            float2 f = __half22float2(*(__half2*)&hv[j]);
            acc.x = fmaf(wt, f.x, acc.x);
            acc.y = fmaf(wt, f.y, acc.y);
        }
    }
    for (; i < end; i++) {
        int sa = __ldg(&g_esrc[i]);
        float wt = __expf(lrelu(__ldg(&g_asrc1[sa * 4 + head]) + adst));
        uint32_t hv = __ldg((const uint32_t*)&g_h1h[(size_t)sa * F1 + coff]);
        s += wt;
        float2 f = __half22float2(*(__half2*)&hv);
        acc.x = fmaf(wt, f.x, acc.x);
        acc.y = fmaf(wt, f.y, acc.y);
    }

    float inv = 1.f / (s + EPSV);
    // this head's 64 channels: h2 = relu(out1 + b1); partial g = h2 @ W2
    float h2a = fmaxf(fmaf(acc.x, inv, __ldg(&b1[coff])), 0.f);
    float h2b = fmaxf(fmaf(acc.y, inv, __ldg(&b1[coff + 1])), 0.f);
    float g0 = h2a * __ldg(&W2[coff * 2 + 0]) + h2b * __ldg(&W2[(coff + 1) * 2 + 0]);
    float g1 = h2a * __ldg(&W2[coff * 2 + 1]) + h2b * __ldg(&W2[(coff + 1) * 2 + 1]);
#pragma unroll
    for (int o = 16; o; o >>= 1) {
        g0 += __shfl_down_sync(0xffffffffu, g0, o);
        g1 += __shfl_down_sync(0xffffffffu, g1, o);
    }
    if (lane == 0) {
        atomicAdd(&g_gg[node * 2 + 0], g0);
        atomicAdd(&g_gg[node * 2 + 1], g1);
    }
}

// ---- finalize layer-2 inputs: pack {asrc2, g0, g1} + adst2 -----------------
__global__ void k_mkpack(const float* __restrict__ as2, const float* __restrict__ ad2, int n) {
    int i = blockIdx.x * blockDim.x + threadIdx.x;
    if (i >= n) return;
    float g0 = g_gg[i * 2 + 0];
    float g1 = g_gg[i * 2 + 1];
    g_pack[i] = make_float4(g0 * __ldg(&as2[0]) + g1 * __ldg(&as2[1]), g0, g1, 0.f);
    g_adst2[i] = g0 * __ldg(&ad2[0]) + g1 * __ldg(&ad2[1]);
}

// ------- Layer 2 aggregation (no-max softmax) + bias + log_softmax ----------
__global__ void k_agg2(float* __restrict__ out, const float* __restrict__ b2, int n) {
    int w = (blockIdx.x * blockDim.x + threadIdx.x) >> 5;
    int lane = threadIdx.x & 31;
    if (w >= n) return;
    float adst = g_adst2[w];
    float s = 0.f, a0 = 0.f, a1 = 0.f;
    if (lane == 0) {   // self-loop
        float4 p = g_pack[w];
        float wS = __expf(lrelu(p.x + adst));
        s = wS;
        a0 = wS * p.y;
        a1 = wS * p.z;
    }
    int beg = g_row[w], end = g_row[w + 1];
    for (int i = beg + lane; i < end; i += 32) {
        int sIdx = __ldg(&g_esrc[i]);
        float4 p = __ldg(&g_pack[sIdx]);
        float we = __expf(lrelu(p.x + adst));
        s += we;
        a0 = fmaf(we, p.y, a0);
        a1 = fmaf(we, p.z, a1);
    }
#pragma unroll
    for (int o = 16; o; o >>= 1) {
        s  += __shfl_down_sync(0xffffffffu, s, o);
        a0 += __shfl_down_sync(0xffffffffu, a0, o);
        a1 += __shfl_down_sync(0xffffffffu, a1, o);
    }
    if (lane == 0) {
        float inv = 1.f / (s + EPSV);
        float v0 = a0 * inv + b2[0];
        float v1 = a1 * inv + b2[1];
        float mm = fmaxf(v0, v1);
        float l = logf(expf(v0 - mm) + expf(v1 - mm)) + mm;
        out[w * 2 + 0] = v0 - l;
        out[w * 2 + 1] = v1 - l;
    }
}

// ---------------------------------------------------------------------------
struct GpuSetup {
    cudaStream_t s2;
    cudaEvent_t eFork, eJoin;
    GpuSetup() {
        cudaStreamCreateWithFlags(&s2, cudaStreamNonBlocking);
        cudaEventCreateWithFlags(&eFork, cudaEventDisableTiming);
        cudaEventCreateWithFlags(&eJoin, cudaEventDisableTiming);
    }
};
static GpuSetup g_setup;

extern "C" void kernel_launch(void* const* d_in, const int* in_sizes, int n_in,
                              void* d_out, int out_size) {
    const float* x   = (const float*)d_in[0];
    const int*   src = (const int*)d_in[1];
    const int*   dst = (const int*)d_in[2];
    const float* W1  = (const float*)d_in[3];
    const float* as1 = (const float*)d_in[4];
    const float* ad1 = (const float*)d_in[5];
    const float* b1  = (const float*)d_in[6];
    const float* W2  = (const float*)d_in[7];
    const float* as2 = (const float*)d_in[8];
    const float* ad2 = (const float*)d_in[9];
    const float* b2  = (const float*)d_in[10];
    float* out = (float*)d_out;

    int n = in_sizes[0] / FIN;   // 100000
    int e = in_sizes[1];         // 1600000
    int nb = (n + 511) / 512;    // scan blocks

    // fork side stream for CSR build (overlaps convert+GEMM)
    cudaEventRecord(g_setup.eFork, 0);
    cudaStreamWaitEvent(g_setup.s2, g_setup.eFork, 0);

    // issue order: slot #3 = k_gemm1_mma (ncu profiles the 4th launch)
    int cvt_total = n * KP + 256 * KP + n * 2;   // x + W + g_gg zero
    k_cvtxw<<<(cvt_total + 255) / 256, 256>>>(x, W1, n);               // 0
    k_zerocnt<<<(n + 255) / 256, 256, 0, g_setup.s2>>>(n);             // 1
    k_count<<<(e + 255) / 256, 256, 0, g_setup.s2>>>(dst, e);          // 2
    {
        dim3 grid(4, (n + 127) / 128);
        k_gemm1_mma<<<grid, 256>>>(as1, ad1, n);                       // 3  <-- profiled
    }
    k_scan1<<<nb, 512, 0, g_setup.s2>>>(n);                            // 4
    k_scan2<<<1, 256, 0, g_setup.s2>>>(n, nb);                         // 5
    k_scan3<<<nb, 512, 0, g_setup.s2>>>(n);                            // 6
    k_scatter<<<(e + 255) / 256, 256, 0, g_setup.s2>>>(src, dst, e);   // 7
    cudaEventRecord(g_setup.eJoin, g_setup.s2);

    cudaStreamWaitEvent(0, g_setup.eJoin, 0);

    k_agg1f<<<(n * 4 * 32 + 255) / 256, 256>>>(b1, W2, n);             // 8
    k_mkpack<<<(n + 255) / 256, 256>>>(as2, ad2, n);                   // 9
    k_agg2<<<(n * 32 + 255) / 256, 256>>>(out, b2, n);                 // 10
}

// round 15
// speedup vs baseline: 1.1675x; 1.1675x over previous
#include <cuda_runtime.h>
#include <cuda_bf16.h>
#include <cuda_fp16.h>
#include <math.h>
#include <stdint.h>

#define NN 100000
#define NE 1600000
#define FIN 165
#define F1  256
#define KP  176            // K padded to multiple of 16
#define KPW (KP/2)         // 32-bit words per row
#define EPSV 1e-16f

// ---------------- scratch (device globals; no allocations allowed) ----------
__device__ __align__(16) __half g_h1h[(size_t)NN * F1];   // fp16 h1 (51 MB)
__device__ __align__(16) float g_asrc1[NN * 4];
__device__ __align__(16) float g_adst1[NN * 4];
__device__ __align__(16) float4 g_pack[NN];               // {asrc2, g0, g1, -}
__device__ float g_adst2[NN];
// bf16 operands (x: hi only; W: hi+lo split — hi+lo is load-bearing, see R10)
__device__ __align__(16) __nv_bfloat16 g_xhi[(size_t)NN * KP];
__device__ __align__(16) __nv_bfloat16 g_whiT[256 * KP];
__device__ __align__(16) __nv_bfloat16 g_wloT[256 * KP];
// CSR scratch
__device__ int g_cnt[NN];
__device__ int g_row[NN + 1];
__device__ int g_cur[NN];
__device__ int g_esrc[NE];
__device__ int g_bsum[256];
__device__ int g_boff[256];

__device__ __forceinline__ float lrelu(float v) { return v > 0.f ? v : 0.2f * v; }

__device__ __forceinline__ void cpa16(uint32_t dst, const void* src, bool valid) {
    asm volatile("cp.async.cg.shared.global [%0], [%1], 16, %2;\n"
                 :: "r"(dst), "l"(src), "r"(valid ? 16 : 0));
}
__device__ __forceinline__ void cpa_commit() {
    asm volatile("cp.async.commit_group;\n");
}
template <int N>
__device__ __forceinline__ void cpa_wait() {
    asm volatile("cp.async.wait_group %0;\n" :: "n"(N));
}
__device__ __forceinline__ void ldsm4(uint32_t* r, uint32_t addr) {
    asm volatile("ldmatrix.sync.aligned.m8n8.x4.shared.b16 {%0,%1,%2,%3}, [%4];"
                 : "=r"(r[0]), "=r"(r[1]), "=r"(r[2]), "=r"(r[3]) : "r"(addr));
}

// --------- operand conversion (x and W fused into one launch) ---------------
__global__ void k_cvtxw(const float* __restrict__ x, const float* __restrict__ W, int n) {
    int i = blockIdx.x * blockDim.x + threadIdx.x;
    int nx = n * KP;
    if (i < nx) {
        int node = i / KP, k = i - node * KP;
        float v = (k < FIN) ? __ldg(&x[(size_t)node * FIN + k]) : 0.f;
        g_xhi[i] = __float2bfloat16(v);
    } else {
        int j = i - nx;
        if (j >= 256 * KP) return;
        int nc = j / KP, k = j - nc * KP;
        float v = (k < FIN) ? W[(size_t)k * 256 + nc] : 0.f;
        __nv_bfloat16 hi = __float2bfloat16(v);
        g_whiT[j] = hi;
        g_wloT[j] = __float2bfloat16(v - __bfloat162float(hi));
    }
}

// ---------------- tensor-core GEMM1 + fused attention scores ----------------
__device__ __forceinline__ void hmma(float* d, const uint32_t* a, const uint32_t* b) {
    asm volatile(
        "mma.sync.aligned.m16n8k16.row.col.f32.bf16.bf16.f32 "
        "{%0,%1,%2,%3},{%4,%5,%6,%7},{%8,%9},{%0,%1,%2,%3};\n"
        : "+f"(d[0]), "+f"(d[1]), "+f"(d[2]), "+f"(d[3])
        : "r"(a[0]), "r"(a[1]), "r"(a[2]), "r"(a[3]), "r"(b[0]), "r"(b[1]));
}

#define XSTRIDE 92          // word stride: 88 kwords + 4 pad (conflict-free ldmatrix)
#define NIT  (KP / 16)      // 11 k-iterations
#define A_WORDS (128 * XSTRIDE)            // 47104 B
#define B_WORDS (64 * XSTRIDE)             // 23552 B
#define GSMEM_BYTES ((A_WORDS + 2 * B_WORDS) * 4)   // 94208 B dynamic

// block: 128 nodes x 64 cols (= one head). 256 threads = 8 warps (4m x 2n).
// Single-stage: whole A (K=176) + B hi/lo resident in smem; ZERO barriers in k-loop.
__global__ void __launch_bounds__(256) k_gemm1_mma(const float* __restrict__ att_s,
                                                   const float* __restrict__ att_d, int n) {
    extern __shared__ uint32_t smem[];
    uint32_t* sA = smem;                       // 128 rows x 92 words
    uint32_t* sBh = smem + A_WORDS;            // 64 rows x 92 words
    uint32_t* sBl = smem + A_WORDS + B_WORDS;  // 64 rows x 92 words
    __shared__ float sS[128], sD[128];
    int bm = blockIdx.y * 128, bn = blockIdx.x * 64, h = bn >> 6;
    int tid = threadIdx.x, lane = tid & 31, wid = tid >> 5;
    int wm = wid & 3, wn = wid >> 2, quad = lane >> 2, t4 = lane & 3;
    if (tid < 128) { sS[tid] = 0.f; sD[tid] = 0.f; }

    const uint32_t* xhi = (const uint32_t*)g_xhi;
    const uint32_t* whi = (const uint32_t*)g_whiT;
    const uint32_t* wlo = (const uint32_t*)g_wloT;

    uint32_t sA_b = (uint32_t)__cvta_generic_to_shared(sA);
    uint32_t sBh_b = (uint32_t)__cvta_generic_to_shared(sBh);
    uint32_t sBl_b = (uint32_t)__cvta_generic_to_shared(sBl);

    // ---- preload B (64 rows x 88 kwords, hi+lo): 1408 16B chunks ----
    for (int c = tid; c < 1408; c += 256) {
        int rowi = (c * 4) / 88;
        int kw = (c * 4) % 88;          // 88 % 4 == 0 -> never crosses rows
        cpa16(sBh_b + (rowi * XSTRIDE + kw) * 4, whi + (size_t)(bn + rowi) * KPW + kw, true);
        cpa16(sBl_b + (rowi * XSTRIDE + kw) * 4, wlo + (size_t)(bn + rowi) * KPW + kw, true);
    }
    // ---- preload ALL of A (128 rows x 88 kwords): 2816 16B chunks ----
    for (int c = tid; c < 2816; c += 256) {
        int rowi = (c * 4) / 88;
        int kw = (c * 4) % 88;
        int node = bm + rowi;
        cpa16(sA_b + (rowi * XSTRIDE + kw) * 4,
              xhi + (size_t)node * KPW + kw, node < n);
    }
    cpa_commit();

    // ldmatrix lane base addresses
    uint32_t aAddr = sA_b + (((wm * 32 + (lane & 15)) * XSTRIDE + ((lane >> 4) & 1) * 4)) * 4;
    uint32_t bRowOff = ((wn * 32 + (lane & 7) + ((lane >> 4) & 1) * 8) * XSTRIDE
                        + ((lane >> 3) & 1) * 4) * 4;
    uint32_t bhAddr = sBh_b + bRowOff;
    uint32_t blAddr = sBl_b + bRowOff;

    float d[2][4][4];
#pragma unroll
    for (int a = 0; a < 2; a++)
#pragma unroll
        for (int b = 0; b < 4; b++)
#pragma unroll
            for (int c = 0; c < 4; c++) d[a][b][c] = 0.f;

    cpa_wait<0>();
    __syncthreads();            // the ONLY barrier before the epilogue

#pragma unroll
    for (int it = 0; it < NIT; it++) {
        uint32_t kb = it * 32;  // 8 words per iter = 32 bytes
        uint32_t ah[2][4], bh01[4], bh23[4], bl01[4], bl23[4];
        ldsm4(ah[0], aAddr + kb);
        ldsm4(ah[1], aAddr + 16 * XSTRIDE * 4 + kb);
        ldsm4(bh01, bhAddr + kb);
        ldsm4(bh23, bhAddr + kb + 16 * XSTRIDE * 4);
        ldsm4(bl01, blAddr + kb);
        ldsm4(bl23, blAddr + kb + 16 * XSTRIDE * 4);

#pragma unroll
        for (int mt = 0; mt < 2; mt++) {
            hmma(d[mt][0], ah[mt], &bh01[0]);
            hmma(d[mt][1], ah[mt], &bh01[2]);
            hmma(d[mt][2], ah[mt], &bh23[0]);
            hmma(d[mt][3], ah[mt], &bh23[2]);
            hmma(d[mt][0], ah[mt], &bl01[0]);
            hmma(d[mt][1], ah[mt], &bl01[2]);
            hmma(d[mt][2], ah[mt], &bl23[0]);
            hmma(d[mt][3], ah[mt], &bl23[2]);
        }
    }

    // store h1 (fp16) + accumulate attention-score partial dots
#pragma unroll
    for (int mt = 0; mt < 2; mt++) {
        int row = wm * 32 + mt * 16 + quad;
        int node0 = bm + row, node1 = node0 + 8;
        float s0 = 0.f, s1 = 0.f, dd0 = 0.f, dd1 = 0.f;
#pragma unroll
        for (int nt = 0; nt < 4; nt++) {
            int c = wn * 32 + nt * 8 + t4 * 2;
            float a0 = __ldg(&att_s[h * 64 + c]), a1 = __ldg(&att_s[h * 64 + c + 1]);
            float e0 = __ldg(&att_d[h * 64 + c]), e1 = __ldg(&att_d[h * 64 + c + 1]);
            s0  += d[mt][nt][0] * a0 + d[mt][nt][1] * a1;
            dd0 += d[mt][nt][0] * e0 + d[mt][nt][1] * e1;
            s1  += d[mt][nt][2] * a0 + d[mt][nt][3] * a1;
            dd1 += d[mt][nt][2] * e0 + d[mt][nt][3] * e1;
            if (node0 < n)
                *(__half2*)&g_h1h[(size_t)node0 * F1 + bn + c] = __floats2half2_rn(d[mt][nt][0], d[mt][nt][1]);
            if (node1 < n)
                *(__half2*)&g_h1h[(size_t)node1 * F1 + bn + c] = __floats2half2_rn(d[mt][nt][2], d[mt][nt][3]);
        }
        s0  += __shfl_xor_sync(0xffffffffu, s0, 1);  s0  += __shfl_xor_sync(0xffffffffu, s0, 2);
        s1  += __shfl_xor_sync(0xffffffffu, s1, 1);  s1  += __shfl_xor_sync(0xffffffffu, s1, 2);
        dd0 += __shfl_xor_sync(0xffffffffu, dd0, 1); dd0 += __shfl_xor_sync(0xffffffffu, dd0, 2);
        dd1 += __shfl_xor_sync(0xffffffffu, dd1, 1); dd1 += __shfl_xor_sync(0xffffffffu, dd1, 2);
        if (t4 == 0) {
            atomicAdd(&sS[row], s0); atomicAdd(&sD[row], dd0);
            atomicAdd(&sS[row + 8], s1); atomicAdd(&sD[row + 8], dd1);
        }
    }
    __syncthreads();
    if (tid < 128) {
        int node = bm + tid;
        if (node < n) {
            g_asrc1[node * 4 + h] = sS[tid];
            g_adst1[node * 4 + h] = sD[tid];
        }
    }
}

// ---------------- CSR build (group edges by dst) -----------------------------
__global__ void k_zerocnt(int n) {
    int i = blockIdx.x * blockDim.x + threadIdx.x;
    if (i < n) g_cnt[i] = 0;
}

__global__ void k_count(const int* __restrict__ dst, int e) {
    int i = blockIdx.x * blockDim.x + threadIdx.x;
    if (i < e) atomicAdd(&g_cnt[dst[i]], 1);
}

__global__ void k_scan1(int n) {
    __shared__ int sh[512];
    int t = threadIdx.x, i = blockIdx.x * 512 + t;
    sh[t] = (i < n) ? g_cnt[i] : 0;
    __syncthreads();
    for (int o = 256; o; o >>= 1) {
        if (t < o) sh[t] += sh[t + o];
        __syncthreads();
    }
    if (t == 0) g_bsum[blockIdx.x] = sh[0];
}

__global__ void k_scan2(int n, int nb) {
    __shared__ int sh[256];
    int t = threadIdx.x;
    int own = (t < nb) ? g_bsum[t] : 0;
    sh[t] = own;
    __syncthreads();
    for (int o = 1; o < 256; o <<= 1) {
        int v = (t >= o) ? sh[t - o] : 0;
        __syncthreads();
        sh[t] += v;
        __syncthreads();
    }
    if (t < nb) g_boff[t] = sh[t] - own;
    if (t == nb - 1) g_row[n] = sh[t];
}

__global__ void k_scan3(int n) {
    __shared__ int sh[512];
    int t = threadIdx.x, i = blockIdx.x * 512 + t;
    int own = (i < n) ? g_cnt[i] : 0;
    sh[t] = own;
    __syncthreads();
    for (int o = 1; o < 512; o <<= 1) {
        int v = (t >= o) ? sh[t - o] : 0;
        __syncthreads();
        sh[t] += v;
        __syncthreads();
    }
    if (i < n) {
        int excl = sh[t] - own + g_boff[blockIdx.x];
        g_row[i] = excl;
        g_cur[i] = excl;
    }
}

__global__ void k_scatter(const int* __restrict__ src, const int* __restrict__ dst, int e) {
    int i = blockIdx.x * blockDim.x + threadIdx.x;
    if (i >= e) return;
    int d = dst[i];
    int pos = atomicAdd(&g_cur[d], 1);
    g_esrc[pos] = src[i];
}

// ---- Layer-1 aggregation (no-max softmax, 4-edge MLP) + fused GEMM2 --------
__global__ void k_agg1f(const float* __restrict__ b1, const float* __restrict__ W2,
                        const float* __restrict__ as2, const float* __restrict__ ad2, int n) {
    int w = (blockIdx.x * blockDim.x + threadIdx.x) >> 5;
    int lane = threadIdx.x & 31;
    if (w >= n) return;
    int h = lane >> 3;
    int ih = w * 4 + h;
    float adst = __ldg(&g_adst1[ih]);

    float s, acc[8];
    {   // self-loop contribution
        float wS = __expf(lrelu(__ldg(&g_asrc1[ih]) + adst));
        s = wS;
        uint4 hv = __ldg((const uint4*)&g_h1h[(size_t)w * F1 + lane * 8]);
        float2 f0 = __half22float2(*(__half2*)&hv.x);
        float2 f1 = __half22float2(*(__half2*)&hv.y);
        float2 f2 = __half22float2(*(__half2*)&hv.z);
        float2 f3 = __half22float2(*(__half2*)&hv.w);
        acc[0] = wS * f0.x; acc[1] = wS * f0.y;
        acc[2] = wS * f1.x; acc[3] = wS * f1.y;
        acc[4] = wS * f2.x; acc[5] = wS * f2.y;
        acc[6] = wS * f3.x; acc[7] = wS * f3.y;
    }

#define ACCUM(WT, HV) { \
        float2 f0 = __half22float2(*(__half2*)&HV.x); \
        float2 f1 = __half22float2(*(__half2*)&HV.y); \
        float2 f2 = __half22float2(*(__half2*)&HV.z); \
        float2 f3 = __half22float2(*(__half2*)&HV.w); \
        acc[0] = fmaf(WT, f0.x, acc[0]); acc[1] = fmaf(WT, f0.y, acc[1]); \
        acc[2] = fmaf(WT, f1.x, acc[2]); acc[3] = fmaf(WT, f1.y, acc[3]); \
        acc[4] = fmaf(WT, f2.x, acc[4]); acc[5] = fmaf(WT, f2.y, acc[5]); \
        acc[6] = fmaf(WT, f3.x, acc[6]); acc[7] = fmaf(WT, f3.y, acc[7]); }

    int beg = g_row[w], end = g_row[w + 1];
    int i = beg;
    for (; i + 3 < end; i += 4) {
        int sidx[4];
#pragma unroll
        for (int j = 0; j < 4; j++) sidx[j] = __ldg(&g_esrc[i + j]);
        float ew[4];
        uint4 hv[4];
#pragma unroll
        for (int j = 0; j < 4; j++) {
            ew[j] = __ldg(&g_asrc1[sidx[j] * 4 + h]);
            hv[j] = __ldg((const uint4*)&g_h1h[(size_t)sidx[j] * F1 + lane * 8]);
        }
#pragma unroll
        for (int j = 0; j < 4; j++) {
            float wt = __expf(lrelu(ew[j] + adst));
            s += wt;
            ACCUM(wt, hv[j]);
        }
    }
    for (; i < end; i++) {
        int sa = __ldg(&g_esrc[i]);
        float wa = __expf(lrelu(__ldg(&g_asrc1[sa * 4 + h]) + adst));
        uint4 va = __ldg((const uint4*)&g_h1h[(size_t)sa * F1 + lane * 8]);
        s += wa;
        ACCUM(wa, va);
    }
#undef ACCUM

    float inv = 1.f / (s + EPSV);
    // fused: h2 = relu(out1 + b1); g = h2 @ W2
    float g0 = 0.f, g1 = 0.f;
#pragma unroll
    for (int j = 0; j < 8; j++) {
        int c = lane * 8 + j;
        float hv = fmaxf(fmaf(acc[j], inv, __ldg(&b1[c])), 0.f);
        g0 = fmaf(hv, __ldg(&W2[c * 2 + 0]), g0);
        g1 = fmaf(hv, __ldg(&W2[c * 2 + 1]), g1);
    }
#pragma unroll
    for (int o = 16; o; o >>= 1) {
        g0 += __shfl_down_sync(0xffffffffu, g0, o);
        g1 += __shfl_down_sync(0xffffffffu, g1, o);
    }
    if (lane == 0) {
        float as = g0 * __ldg(&as2[0]) + g1 * __ldg(&as2[1]);
        g_pack[w] = make_float4(as, g0, g1, 0.f);
        g_adst2[w] = g0 * __ldg(&ad2[0]) + g1 * __ldg(&ad2[1]);
    }
}

// ------- Layer 2 aggregation (no-max softmax) + bias + log_softmax ----------
__global__ void k_agg2(float* __restrict__ out, const float* __restrict__ b2, int n) {
    int w = (blockIdx.x * blockDim.x + threadIdx.x) >> 5;
    int lane = threadIdx.x & 31;
    if (w >= n) return;
    float adst = g_adst2[w];
    float s = 0.f, a0 = 0.f, a1 = 0.f;
    if (lane == 0) {   // self-loop
        float4 p = g_pack[w];
        float wS = __expf(lrelu(p.x + adst));
        s = wS;
        a0 = wS * p.y;
        a1 = wS * p.z;
    }
    int beg = g_row[w], end = g_row[w + 1];
    for (int i = beg + lane; i < end; i += 32) {
        int sIdx = __ldg(&g_esrc[i]);
        float4 p = __ldg(&g_pack[sIdx]);
        float we = __expf(lrelu(p.x + adst));
        s += we;
        a0 = fmaf(we, p.y, a0);
        a1 = fmaf(we, p.z, a1);
    }
#pragma unroll
    for (int o = 16; o; o >>= 1) {
        s  += __shfl_down_sync(0xffffffffu, s, o);
        a0 += __shfl_down_sync(0xffffffffu, a0, o);
        a1 += __shfl_down_sync(0xffffffffu, a1, o);
    }
    if (lane == 0) {
        float inv = 1.f / (s + EPSV);
        float v0 = a0 * inv + b2[0];
        float v1 = a1 * inv + b2[1];
        float mm = fmaxf(v0, v1);
        float l = logf(expf(v0 - mm) + expf(v1 - mm)) + mm;
        out[w * 2 + 0] = v0 - l;
        out[w * 2 + 1] = v1 - l;
    }
}

// ---------------------------------------------------------------------------
struct GpuSetup {
    cudaStream_t s2;
    cudaEvent_t eFork, eJoin;
    GpuSetup() {
        cudaStreamCreateWithFlags(&s2, cudaStreamNonBlocking);
        cudaEventCreateWithFlags(&eFork, cudaEventDisableTiming);
        cudaEventCreateWithFlags(&eJoin, cudaEventDisableTiming);
        cudaFuncSetAttribute(k_gemm1_mma,
                             cudaFuncAttributeMaxDynamicSharedMemorySize, GSMEM_BYTES);
    }
};
static GpuSetup g_setup;

extern "C" void kernel_launch(void* const* d_in, const int* in_sizes, int n_in,
                              void* d_out, int out_size) {
    const float* x   = (const float*)d_in[0];
    const int*   src = (const int*)d_in[1];
    const int*   dst = (const int*)d_in[2];
    const float* W1  = (const float*)d_in[3];
    const float* as1 = (const float*)d_in[4];
    const float* ad1 = (const float*)d_in[5];
    const float* b1  = (const float*)d_in[6];
    const float* W2  = (const float*)d_in[7];
    const float* as2 = (const float*)d_in[8];
    const float* ad2 = (const float*)d_in[9];
    const float* b2  = (const float*)d_in[10];
    float* out = (float*)d_out;

    int n = in_sizes[0] / FIN;   // 100000
    int e = in_sizes[1];         // 1600000
    int nb = (n + 511) / 512;    // scan blocks

    // fork side stream for CSR build (overlaps convert+GEMM)
    cudaEventRecord(g_setup.eFork, 0);
    cudaStreamWaitEvent(g_setup.s2, g_setup.eFork, 0);

    // issue order: slot #3 = k_gemm1_mma (ncu profiles the 4th launch)
    int cvt_total = n * KP + 256 * KP;
    k_cvtxw<<<(cvt_total + 255) / 256, 256>>>(x, W1, n);               // 0
    k_zerocnt<<<(n + 255) / 256, 256, 0, g_setup.s2>>>(n);             // 1
    k_count<<<(e + 255) / 256, 256, 0, g_setup.s2>>>(dst, e);          // 2
    {
        dim3 grid(4, (n + 127) / 128);
        k_gemm1_mma<<<grid, 256, GSMEM_BYTES>>>(as1, ad1, n);          // 3  <-- profiled
    }
    k_scan1<<<nb, 512, 0, g_setup.s2>>>(n);                            // 4
    k_scan2<<<1, 256, 0, g_setup.s2>>>(n, nb);                         // 5
    k_scan3<<<nb, 512, 0, g_setup.s2>>>(n);                            // 6
    k_scatter<<<(e + 255) / 256, 256, 0, g_setup.s2>>>(src, dst, e);   // 7
    cudaEventRecord(g_setup.eJoin, g_setup.s2);

    cudaStreamWaitEvent(0, g_setup.eJoin, 0);

    k_agg1f<<<(n * 32 + 255) / 256, 256>>>(b1, W2, as2, ad2, n);       // 8
    k_agg2<<<(n * 32 + 255) / 256, 256>>>(out, b2, n);                 // 9
}